// round 13
// baseline (speedup 1.0000x reference)
#include <cuda_runtime.h>
#include <cuda_fp16.h>
#include <cstdint>

#define Nn 2304
#define Cc 192
#define QTQ 128        // queries per CTA
#define KTILE 144      // keys per tile (3 X-rows)
#define NTILES 16
#define KROW2 2308     // KT2 row stride in float2 (>=2304, ==4 mod 16: conflict-free)
#define VROW2 580      // V2 row stride in uint2  (==4 mod 16: conflict-free)
#define SL2E 0.5100420914154871f

// smem float-word offsets
#define W_KT2  0                       // float2 [4][KROW2]  (k_d, k_{d+4}) per key
#define W_V2   (4*KROW2*2)             // uint2  [8][VROW2]  ((pair p),(pair p+4))
#define W_PH   (W_V2 + 8*VROW2*2)      // phT[128][49]
#define W_PW   (W_PH + 128*49)         // pwT[128][50]
#define W_OS   (W_PW + 128*50)         // O partials [3][128][8]
#define W_SS   (W_OS + 3*128*8)        // sums [3][128]
#define SMEM_BYTES ((W_SS + 3*128)*4)

__device__ __forceinline__ float ex2f(float x){
    float r; asm("ex2.approx.f32 %0,%1;" : "=f"(r) : "f"(x)); return r;
}
__device__ __forceinline__ float tf32r(float x){
    uint32_t r; asm("cvt.rna.tf32.f32 %0,%1;" : "=r"(r) : "f"(x));
    return __uint_as_float(r);
}
__device__ __forceinline__ uint32_t pkh2(float lo, float hi){
    __half2 h = __floats2half2_rn(lo, hi);
    return *(uint32_t*)&h;
}
__device__ __forceinline__ void mma_tf32(
    float& d0, float& d1, float& d2, float& d3,
    uint32_t a0, uint32_t a1, uint32_t a2, uint32_t a3,
    uint32_t b0, uint32_t b1)
{
    asm volatile(
        "mma.sync.aligned.m16n8k8.row.col.f32.tf32.tf32.f32 "
        "{%0,%1,%2,%3},{%4,%5,%6,%7},{%8,%9},{%10,%11,%12,%13};"
        : "=f"(d0),"=f"(d1),"=f"(d2),"=f"(d3)
        : "r"(a0),"r"(a1),"r"(a2),"r"(a3),"r"(b0),"r"(b1),
          "f"(0.f),"f"(0.f),"f"(0.f),"f"(0.f));
}
__device__ __forceinline__ void mma_f16(
    float& d0, float& d1, float& d2, float& d3,
    uint32_t a0, uint32_t a1, uint32_t a2, uint32_t a3,
    uint32_t b0, uint32_t b1,
    float c0, float c1, float c2, float c3)
{
    asm volatile(
        "mma.sync.aligned.m16n8k16.row.col.f32.f16.f16.f32 "
        "{%0,%1,%2,%3},{%4,%5,%6,%7},{%8,%9},{%10,%11,%12,%13};"
        : "=f"(d0),"=f"(d1),"=f"(d2),"=f"(d3)
        : "r"(a0),"r"(a1),"r"(a2),"r"(a3),"r"(b0),"r"(b1),
          "f"(c0),"f"(c1),"f"(c2),"f"(c3));
}

__global__ __launch_bounds__(768, 1)
void attn_aug2d_mma(const float* __restrict__ inp,
                    const float* __restrict__ relw,
                    const float* __restrict__ relh,
                    float* __restrict__ out)
{
    extern __shared__ float sm[];
    float2* KT2 = (float2*)sm;
    uint2*  V2  = (uint2*)(sm + W_V2);
    const int tid  = threadIdx.x;
    const int warp = tid >> 5;
    const int lane = tid & 31;
    const int g    = lane >> 2;
    const int t    = lane & 3;
    const int strip = warp >> 3;        // 0..2
    const int mrow  = (warp & 7) << 4;
    const int h = blockIdx.y, b = blockIdx.z;
    const int qbase = blockIdx.x * QTQ;

    // ---- stage K transposed, interleaved (d, d+4) float2 per key ----
    for (int key = tid; key < Nn; key += 768){
        const float* p = inp + ((size_t)(b*Nn + key))*Cc + h*8 + 64;
        float4 k0 = *(const float4*)(p);
        float4 k1 = *(const float4*)(p + 4);
        KT2[0*KROW2 + key] = make_float2(tf32r(k0.x), tf32r(k1.x));
        KT2[1*KROW2 + key] = make_float2(tf32r(k0.y), tf32r(k1.y));
        KT2[2*KROW2 + key] = make_float2(tf32r(k0.z), tf32r(k1.z));
        KT2[3*KROW2 + key] = make_float2(tf32r(k0.w), tf32r(k1.w));
    }
    // ---- stage V as paired f16x2: entry e=(blk,t4) packs pairs (blk*8+t4, +4) ----
    for (int e = tid; e < 576; e += 768){
        int blk = e >> 2, t4 = e & 3;
        int p0 = blk*8 + t4, p1 = p0 + 4;
        const float* A0 = inp + ((size_t)(b*Nn + 2*p0))*Cc + h*8 + 128;
        const float* A1 = A0 + Cc;
        const float* B0 = inp + ((size_t)(b*Nn + 2*p1))*Cc + h*8 + 128;
        const float* B1 = B0 + Cc;
        float4 a0 = *(const float4*)A0, a0h = *(const float4*)(A0+4);
        float4 a1 = *(const float4*)A1, a1h = *(const float4*)(A1+4);
        float4 b0 = *(const float4*)B0, b0h = *(const float4*)(B0+4);
        float4 b1 = *(const float4*)B1, b1h = *(const float4*)(B1+4);
        V2[0*VROW2 + e] = make_uint2(pkh2(a0.x,a1.x),  pkh2(b0.x,b1.x));
        V2[1*VROW2 + e] = make_uint2(pkh2(a0.y,a1.y),  pkh2(b0.y,b1.y));
        V2[2*VROW2 + e] = make_uint2(pkh2(a0.z,a1.z),  pkh2(b0.z,b1.z));
        V2[3*VROW2 + e] = make_uint2(pkh2(a0.w,a1.w),  pkh2(b0.w,b1.w));
        V2[4*VROW2 + e] = make_uint2(pkh2(a0h.x,a1h.x),pkh2(b0h.x,b1h.x));
        V2[5*VROW2 + e] = make_uint2(pkh2(a0h.y,a1h.y),pkh2(b0h.y,b1h.y));
        V2[6*VROW2 + e] = make_uint2(pkh2(a0h.z,a1h.z),pkh2(b0h.z,b1h.z));
        V2[7*VROW2 + e] = make_uint2(pkh2(a0h.w,a1h.w),pkh2(b0h.w,b1h.w));
    }

    // ---- bias tables: broadcast-friendly mapping ----
    // thread -> (q = tid&127, chunk = tid>>7). Each thread: its q-row (2 LDG.128),
    // then 16 of 96 (table,pos) entries; rel-row loads are warp-broadcast.
    {
        const int q  = tid & 127;
        const int ck = tid >> 7;          // 0..5 (0-2: ph, 3-5: pw) — warp-uniform
        const int n  = qbase + q;
        const int x  = n / 48, y = n - x*48;
        const float* qp = inp + ((size_t)(b*Nn + n))*Cc + h*8;
        float4 q0 = *(const float4*)(qp);
        float4 q1 = *(const float4*)(qp + 4);
        const int isw  = (ck >= 3);
        const int pos0 = (ck - isw*3) * 16;
        const int roff = isw ? -y : -x;
        const float* relT = isw ? relw : relh;
        float* dst = isw ? (sm + W_PW + q*50) : (sm + W_PH + q*49);
        #pragma unroll 4
        for (int ii = 0; ii < 16; ii++){
            int pos = pos0 + ii;
            const float* rel = relT + (pos + roff + 47)*8;
            float4 r0 = *(const float4*)(rel);
            float4 r1 = *(const float4*)(rel + 4);
            float s = q0.x*r0.x + q0.y*r0.y + q0.z*r0.z + q0.w*r0.w
                    + q1.x*r1.x + q1.y*r1.y + q1.z*r1.z + q1.w*r1.w;
            dst[pos] = s * SL2E;
        }
    }

    // ---- Q fragment (GEMM1 A), tf32, pre-scaled ----
    const int qa = mrow + g, qb = qa + 8;
    const float* qpa = inp + ((size_t)(b*Nn + qbase + qa))*Cc + h*8;
    const float* qpb = inp + ((size_t)(b*Nn + qbase + qb))*Cc + h*8;
    const uint32_t aq0 = __float_as_uint(tf32r(qpa[t]   * SL2E));
    const uint32_t aq1 = __float_as_uint(tf32r(qpb[t]   * SL2E));
    const uint32_t aq2 = __float_as_uint(tf32r(qpa[t+4] * SL2E));
    const uint32_t aq3 = __float_as_uint(tf32r(qpb[t+4] * SL2E));

    __syncthreads();

    // ---- pw bias: tile-invariant -> hoist into registers ----
    float2 pal[3], pbl[3], pah[3], pbh[3];
    #pragma unroll
    for (int jj = 0; jj < 3; jj++){
        const int Y = 16*jj + 2*t;
        pal[jj] = *(const float2*)&sm[W_PW + qa*50 + Y];
        pbl[jj] = *(const float2*)&sm[W_PW + qb*50 + Y];
        pah[jj] = *(const float2*)&sm[W_PW + qa*50 + Y + 8];
        pbh[jj] = *(const float2*)&sm[W_PW + qb*50 + Y + 8];
    }

    float o0=0.f, o1=0.f, o2=0.f, o3=0.f;
    float sum0=0.f, sum1=0.f;

    for (int tile = 0; tile < NTILES; tile++){
        const int X     = 3*tile + strip;
        const int K0t   = tile*KTILE + strip*48;
        const int Vbase = tile*36 + strip*12;
        const float pha = sm[W_PH + qa*49 + X];
        const float phb = sm[W_PH + qb*49 + X];

        #pragma unroll
        for (int jj = 0; jj < 3; jj++){
            const int K0 = K0t + 16*jj;
            float2 kl = KT2[t*KROW2 + K0 + g];
            float2 kh = KT2[t*KROW2 + K0 + 8 + g];
            float l0,l1,l2,l3, h0,h1,h2,h3;
            mma_tf32(l0,l1,l2,l3, aq0,aq1,aq2,aq3,
                     __float_as_uint(kl.x), __float_as_uint(kl.y));
            mma_tf32(h0,h1,h2,h3, aq0,aq1,aq2,aq3,
                     __float_as_uint(kh.x), __float_as_uint(kh.y));

            float wl0 = ex2f(l0 + pha + pal[jj].x);
            float wl1 = ex2f(l1 + pha + pal[jj].y);
            float wl2 = ex2f(l2 + phb + pbl[jj].x);
            float wl3 = ex2f(l3 + phb + pbl[jj].y);
            float wh0 = ex2f(h0 + pha + pah[jj].x);
            float wh1 = ex2f(h1 + pha + pah[jj].y);
            float wh2 = ex2f(h2 + phb + pbh[jj].x);
            float wh3 = ex2f(h3 + phb + pbh[jj].y);
            sum0 += (wl0 + wl1) + (wh0 + wh1);
            sum1 += (wl2 + wl3) + (wh2 + wh3);

            uint32_t a0 = pkh2(wl0, wl1);
            uint32_t a1 = pkh2(wl2, wl3);
            uint32_t a2 = pkh2(wh0, wh1);
            uint32_t a3 = pkh2(wh2, wh3);

            uint2 vv = V2[g*VROW2 + Vbase + 4*jj + t];
            mma_f16(o0,o1,o2,o3, a0,a1,a2,a3, vv.x, vv.y, o0,o1,o2,o3);
        }
    }

    // ---- reduce sums within t-group ----
    sum0 += __shfl_xor_sync(0xffffffffu, sum0, 1);
    sum0 += __shfl_xor_sync(0xffffffffu, sum0, 2);
    sum1 += __shfl_xor_sync(0xffffffffu, sum1, 1);
    sum1 += __shfl_xor_sync(0xffffffffu, sum1, 2);
    if (t == 0){
        sm[W_SS + strip*128 + qa] = sum0;
        sm[W_SS + strip*128 + qb] = sum1;
    }
    *(float2*)&sm[W_OS + strip*1024 + qa*8 + 2*t] = make_float2(o0, o1);
    *(float2*)&sm[W_OS + strip*1024 + qb*8 + 2*t] = make_float2(o2, o3);
    __syncthreads();

    // ---- combine strips, normalize, write ----
    if (tid < 128){
        int q = tid;
        float r = 1.0f / (sm[W_SS + q] + sm[W_SS + 128 + q] + sm[W_SS + 256 + q]);
        float* op = out + ((size_t)(b*Nn + qbase + q))*64 + h*8;
        #pragma unroll
        for (int half = 0; half < 2; half++){
            float4 A = *(float4*)&sm[W_OS +        q*8 + half*4];
            float4 B = *(float4*)&sm[W_OS + 1024 + q*8 + half*4];
            float4 C = *(float4*)&sm[W_OS + 2048 + q*8 + half*4];
            ((float4*)op)[half] = make_float4((A.x+B.x+C.x)*r, (A.y+B.y+C.y)*r,
                                              (A.z+B.z+C.z)*r, (A.w+B.w+C.w)*r);
        }
    }
}

extern "C" void kernel_launch(void* const* d_in, const int* in_sizes, int n_in,
                              void* d_out, int out_size)
{
    const float* inp  = (const float*)d_in[0];
    const float* relw = (const float*)d_in[1];
    const float* relh = (const float*)d_in[2];
    float* out = (float*)d_out;

    cudaFuncSetAttribute(attn_aug2d_mma,
                         cudaFuncAttributeMaxDynamicSharedMemorySize, SMEM_BYTES);
    dim3 grid(Nn/QTQ, 8, 2);
    attn_aug2d_mma<<<grid, 768, SMEM_BYTES>>>(inp, relw, relh, out);
}

// round 14
// speedup vs baseline: 1.6026x; 1.6026x over previous
#include <cuda_runtime.h>
#include <cuda_fp16.h>
#include <cstdint>

#define Nn 2304
#define Cc 192
#define QTQ 128        // queries per CTA
#define KTILE 144      // keys per tile (3 X-rows)
#define NTILES 16
#define KROW2 2308     // KT2 row stride in float2 (>=2304, ==4 mod 16: conflict-free)
#define VROW2 580      // V2 row stride in uint2  (==4 mod 16: conflict-free)
#define SL2E 0.5100420914154871f

// smem float-word offsets
#define W_KT2  0                       // float2 [4][KROW2]  (k_d, k_{d+4}) per key
#define W_V2   (4*KROW2*2)             // uint2  [8][VROW2]  ((pair p),(pair p+4))
#define W_PH   (W_V2 + 8*VROW2*2)      // phT[128][49]
#define W_PW   (W_PH + 128*49)         // pwT[128][50]
#define W_OS   (W_PW + 128*50)         // O partials [3][128][8]
#define W_SS   (W_OS + 3*128*8)        // sums [3][128]
#define SMEM_BYTES ((W_SS + 3*128)*4)

__device__ __forceinline__ float ex2f(float x){
    float r; asm("ex2.approx.f32 %0,%1;" : "=f"(r) : "f"(x)); return r;
}
__device__ __forceinline__ float tf32r(float x){
    uint32_t r; asm("cvt.rna.tf32.f32 %0,%1;" : "=r"(r) : "f"(x));
    return __uint_as_float(r);
}
__device__ __forceinline__ uint32_t pkh2(float lo, float hi){
    __half2 h = __floats2half2_rn(lo, hi);
    return *(uint32_t*)&h;
}
// tf32 MMA with bias preloaded in the C operand
__device__ __forceinline__ void mma_tf32c(
    float& d0, float& d1, float& d2, float& d3,
    uint32_t a0, uint32_t a1, uint32_t a2, uint32_t a3,
    uint32_t b0, uint32_t b1,
    float c0, float c1, float c2, float c3)
{
    asm volatile(
        "mma.sync.aligned.m16n8k8.row.col.f32.tf32.tf32.f32 "
        "{%0,%1,%2,%3},{%4,%5,%6,%7},{%8,%9},{%10,%11,%12,%13};"
        : "=f"(d0),"=f"(d1),"=f"(d2),"=f"(d3)
        : "r"(a0),"r"(a1),"r"(a2),"r"(a3),"r"(b0),"r"(b1),
          "f"(c0),"f"(c1),"f"(c2),"f"(c3));
}
__device__ __forceinline__ void mma_f16(
    float& d0, float& d1, float& d2, float& d3,
    uint32_t a0, uint32_t a1, uint32_t a2, uint32_t a3,
    uint32_t b0, uint32_t b1,
    float c0, float c1, float c2, float c3)
{
    asm volatile(
        "mma.sync.aligned.m16n8k16.row.col.f32.f16.f16.f32 "
        "{%0,%1,%2,%3},{%4,%5,%6,%7},{%8,%9},{%10,%11,%12,%13};"
        : "=f"(d0),"=f"(d1),"=f"(d2),"=f"(d3)
        : "r"(a0),"r"(a1),"r"(a2),"r"(a3),"r"(b0),"r"(b1),
          "f"(c0),"f"(c1),"f"(c2),"f"(c3));
}

__global__ __launch_bounds__(768, 1)
void attn_aug2d_mma(const float* __restrict__ inp,
                    const float* __restrict__ relw,
                    const float* __restrict__ relh,
                    float* __restrict__ out)
{
    extern __shared__ float sm[];
    float2* KT2 = (float2*)sm;
    uint2*  V2  = (uint2*)(sm + W_V2);
    const int tid  = threadIdx.x;
    const int warp = tid >> 5;
    const int lane = tid & 31;
    const int g    = lane >> 2;
    const int t    = lane & 3;
    const int strip = warp >> 3;        // 0..2
    const int mrow  = (warp & 7) << 4;
    const int h = blockIdx.y, b = blockIdx.z;
    const int qbase = blockIdx.x * QTQ;

    // ---- stage K transposed, interleaved (d, d+4) float2 per key ----
    for (int key = tid; key < Nn; key += 768){
        const float* p = inp + ((size_t)(b*Nn + key))*Cc + h*8 + 64;
        float4 k0 = *(const float4*)(p);
        float4 k1 = *(const float4*)(p + 4);
        KT2[0*KROW2 + key] = make_float2(tf32r(k0.x), tf32r(k1.x));
        KT2[1*KROW2 + key] = make_float2(tf32r(k0.y), tf32r(k1.y));
        KT2[2*KROW2 + key] = make_float2(tf32r(k0.z), tf32r(k1.z));
        KT2[3*KROW2 + key] = make_float2(tf32r(k0.w), tf32r(k1.w));
    }
    // ---- stage V as paired f16x2: entry e=(blk,t4) packs pairs (blk*8+t4, +4) ----
    for (int e = tid; e < 576; e += 768){
        int blk = e >> 2, t4 = e & 3;
        int p0 = blk*8 + t4, p1 = p0 + 4;
        const float* A0 = inp + ((size_t)(b*Nn + 2*p0))*Cc + h*8 + 128;
        const float* A1 = A0 + Cc;
        const float* B0 = inp + ((size_t)(b*Nn + 2*p1))*Cc + h*8 + 128;
        const float* B1 = B0 + Cc;
        float4 a0 = *(const float4*)A0, a0h = *(const float4*)(A0+4);
        float4 a1 = *(const float4*)A1, a1h = *(const float4*)(A1+4);
        float4 b0 = *(const float4*)B0, b0h = *(const float4*)(B0+4);
        float4 b1 = *(const float4*)B1, b1h = *(const float4*)(B1+4);
        V2[0*VROW2 + e] = make_uint2(pkh2(a0.x,a1.x),  pkh2(b0.x,b1.x));
        V2[1*VROW2 + e] = make_uint2(pkh2(a0.y,a1.y),  pkh2(b0.y,b1.y));
        V2[2*VROW2 + e] = make_uint2(pkh2(a0.z,a1.z),  pkh2(b0.z,b1.z));
        V2[3*VROW2 + e] = make_uint2(pkh2(a0.w,a1.w),  pkh2(b0.w,b1.w));
        V2[4*VROW2 + e] = make_uint2(pkh2(a0h.x,a1h.x),pkh2(b0h.x,b1h.x));
        V2[5*VROW2 + e] = make_uint2(pkh2(a0h.y,a1h.y),pkh2(b0h.y,b1h.y));
        V2[6*VROW2 + e] = make_uint2(pkh2(a0h.z,a1h.z),pkh2(b0h.z,b1h.z));
        V2[7*VROW2 + e] = make_uint2(pkh2(a0h.w,a1h.w),pkh2(b0h.w,b1h.w));
    }

    // ---- bias tables: broadcast-friendly mapping ----
    {
        const int q  = tid & 127;
        const int ck = tid >> 7;          // 0..5 (0-2: ph, 3-5: pw) — warp-uniform
        const int n  = qbase + q;
        const int x  = n / 48, y = n - x*48;
        const float* qp = inp + ((size_t)(b*Nn + n))*Cc + h*8;
        float4 q0 = *(const float4*)(qp);
        float4 q1 = *(const float4*)(qp + 4);
        const int isw  = (ck >= 3);
        const int pos0 = (ck - isw*3) * 16;
        const int roff = isw ? -y : -x;
        const float* relT = isw ? relw : relh;
        float* dst = isw ? (sm + W_PW + q*50) : (sm + W_PH + q*49);
        #pragma unroll 4
        for (int ii = 0; ii < 16; ii++){
            int pos = pos0 + ii;
            const float* rel = relT + (pos + roff + 47)*8;
            float4 r0 = *(const float4*)(rel);
            float4 r1 = *(const float4*)(rel + 4);
            float s = q0.x*r0.x + q0.y*r0.y + q0.z*r0.z + q0.w*r0.w
                    + q1.x*r1.x + q1.y*r1.y + q1.z*r1.z + q1.w*r1.w;
            dst[pos] = s * SL2E;
        }
    }

    // ---- Q fragment (GEMM1 A), tf32, pre-scaled ----
    const int qa = mrow + g, qb = qa + 8;
    const float* qpa = inp + ((size_t)(b*Nn + qbase + qa))*Cc + h*8;
    const float* qpb = inp + ((size_t)(b*Nn + qbase + qb))*Cc + h*8;
    const uint32_t aq0 = __float_as_uint(tf32r(qpa[t]   * SL2E));
    const uint32_t aq1 = __float_as_uint(tf32r(qpb[t]   * SL2E));
    const uint32_t aq2 = __float_as_uint(tf32r(qpa[t+4] * SL2E));
    const uint32_t aq3 = __float_as_uint(tf32r(qpb[t+4] * SL2E));

    __syncthreads();

    // ---- pw bias: tile-invariant -> hoist into registers ----
    float2 pal[3], pbl[3], pah[3], pbh[3];
    #pragma unroll
    for (int jj = 0; jj < 3; jj++){
        const int Y = 16*jj + 2*t;
        pal[jj] = *(const float2*)&sm[W_PW + qa*50 + Y];
        pbl[jj] = *(const float2*)&sm[W_PW + qb*50 + Y];
        pah[jj] = *(const float2*)&sm[W_PW + qa*50 + Y + 8];
        pbh[jj] = *(const float2*)&sm[W_PW + qb*50 + Y + 8];
    }

    float o0=0.f, o1=0.f, o2=0.f, o3=0.f;
    float sum0=0.f, sum1=0.f;

    for (int tile = 0; tile < NTILES; tile++){
        const int X     = 3*tile + strip;
        const int K0t   = tile*KTILE + strip*48;
        const int Vbase = tile*36 + strip*12;
        const float pha = sm[W_PH + qa*49 + X];
        const float phb = sm[W_PH + qb*49 + X];

        #pragma unroll
        for (int jj = 0; jj < 3; jj++){
            const int K0 = K0t + 16*jj;
            float2 kl = KT2[t*KROW2 + K0 + g];
            float2 kh = KT2[t*KROW2 + K0 + 8 + g];

            // bias goes in through the MMA C operand
            float l0,l1,l2,l3, h0,h1,h2,h3;
            mma_tf32c(l0,l1,l2,l3, aq0,aq1,aq2,aq3,
                      __float_as_uint(kl.x), __float_as_uint(kl.y),
                      pha + pal[jj].x, pha + pal[jj].y,
                      phb + pbl[jj].x, phb + pbl[jj].y);
            mma_tf32c(h0,h1,h2,h3, aq0,aq1,aq2,aq3,
                      __float_as_uint(kh.x), __float_as_uint(kh.y),
                      pha + pah[jj].x, pha + pah[jj].y,
                      phb + pbh[jj].x, phb + pbh[jj].y);

            float wl0 = ex2f(l0);
            float wl1 = ex2f(l1);
            float wl2 = ex2f(l2);
            float wl3 = ex2f(l3);
            float wh0 = ex2f(h0);
            float wh1 = ex2f(h1);
            float wh2 = ex2f(h2);
            float wh3 = ex2f(h3);
            sum0 += (wl0 + wl1) + (wh0 + wh1);
            sum1 += (wl2 + wl3) + (wh2 + wh3);

            uint32_t a0 = pkh2(wl0, wl1);
            uint32_t a1 = pkh2(wl2, wl3);
            uint32_t a2 = pkh2(wh0, wh1);
            uint32_t a3 = pkh2(wh2, wh3);

            uint2 vv = V2[g*VROW2 + Vbase + 4*jj + t];
            mma_f16(o0,o1,o2,o3, a0,a1,a2,a3, vv.x, vv.y, o0,o1,o2,o3);
        }
    }

    // ---- reduce sums within t-group ----
    sum0 += __shfl_xor_sync(0xffffffffu, sum0, 1);
    sum0 += __shfl_xor_sync(0xffffffffu, sum0, 2);
    sum1 += __shfl_xor_sync(0xffffffffu, sum1, 1);
    sum1 += __shfl_xor_sync(0xffffffffu, sum1, 2);
    if (t == 0){
        sm[W_SS + strip*128 + qa] = sum0;
        sm[W_SS + strip*128 + qb] = sum1;
    }
    *(float2*)&sm[W_OS + strip*1024 + qa*8 + 2*t] = make_float2(o0, o1);
    *(float2*)&sm[W_OS + strip*1024 + qb*8 + 2*t] = make_float2(o2, o3);
    __syncthreads();

    // ---- combine strips, normalize, write ----
    if (tid < 128){
        int q = tid;
        float r = 1.0f / (sm[W_SS + q] + sm[W_SS + 128 + q] + sm[W_SS + 256 + q]);
        float* op = out + ((size_t)(b*Nn + qbase + q))*64 + h*8;
        #pragma unroll
        for (int half = 0; half < 2; half++){
            float4 A = *(float4*)&sm[W_OS +        q*8 + half*4];
            float4 B = *(float4*)&sm[W_OS + 1024 + q*8 + half*4];
            float4 C = *(float4*)&sm[W_OS + 2048 + q*8 + half*4];
            ((float4*)op)[half] = make_float4((A.x+B.x+C.x)*r, (A.y+B.y+C.y)*r,
                                              (A.z+B.z+C.z)*r, (A.w+B.w+C.w)*r);
        }
    }
}

extern "C" void kernel_launch(void* const* d_in, const int* in_sizes, int n_in,
                              void* d_out, int out_size)
{
    const float* inp  = (const float*)d_in[0];
    const float* relw = (const float*)d_in[1];
    const float* relh = (const float*)d_in[2];
    float* out = (float*)d_out;

    cudaFuncSetAttribute(attn_aug2d_mma,
                         cudaFuncAttributeMaxDynamicSharedMemorySize, SMEM_BYTES);
    dim3 grid(Nn/QTQ, 8, 2);
    attn_aug2d_mma<<<grid, 768, SMEM_BYTES>>>(inp, relw, relh, out);
}

// round 15
// speedup vs baseline: 1.8275x; 1.1403x over previous
#include <cuda_runtime.h>
#include <cuda_fp16.h>
#include <cstdint>

#define Nn 2304
#define Cc 192
#define QTQ 128        // queries per CTA
#define KTILE 144      // keys per tile (3 X-rows)
#define NTILES 16
#define KROW2 2308     // KT2 row stride in float2 (==4 mod 16: conflict-free)
#define VROW2 580      // V2 row stride in uint2  (==4 mod 16: conflict-free)
#define SL2E 0.5100420914154871f
#define ONES16 0x3C003C00u

// smem float-word offsets
#define W_KT2  0                       // float2 [4][KROW2]
#define W_V2   (4*KROW2*2)             // uint2  [8][VROW2]
#define W_PH   (W_V2 + 8*VROW2*2)      // phT[128][49]
#define W_PW   (W_PH + 128*49)         // pwT[128][50]
#define W_OS   (W_PW + 128*50)         // O partials [3][128][8]
#define W_SS   (W_OS + 3*128*8)        // sums [3][128]
#define SMEM_BYTES ((W_SS + 3*128)*4)

__device__ __forceinline__ float tf32r(float x){
    uint32_t r; asm("cvt.rna.tf32.f32 %0,%1;" : "=r"(r) : "f"(x));
    return __uint_as_float(r);
}
__device__ __forceinline__ uint32_t pkh2(float lo, float hi){
    __half2 h = __floats2half2_rn(lo, hi);
    return *(uint32_t*)&h;
}
__device__ __forceinline__ uint32_t ex2h2(uint32_t x){
    uint32_t r; asm("ex2.approx.f16x2 %0,%1;" : "=r"(r) : "r"(x));
    return r;
}
__device__ __forceinline__ void mma_tf32c(
    float& d0, float& d1, float& d2, float& d3,
    uint32_t a0, uint32_t a1, uint32_t a2, uint32_t a3,
    uint32_t b0, uint32_t b1,
    float c0, float c1, float c2, float c3)
{
    asm volatile(
        "mma.sync.aligned.m16n8k8.row.col.f32.tf32.tf32.f32 "
        "{%0,%1,%2,%3},{%4,%5,%6,%7},{%8,%9},{%10,%11,%12,%13};"
        : "=f"(d0),"=f"(d1),"=f"(d2),"=f"(d3)
        : "r"(a0),"r"(a1),"r"(a2),"r"(a3),"r"(b0),"r"(b1),
          "f"(c0),"f"(c1),"f"(c2),"f"(c3));
}
__device__ __forceinline__ void mma_f16(
    float& d0, float& d1, float& d2, float& d3,
    uint32_t a0, uint32_t a1, uint32_t a2, uint32_t a3,
    uint32_t b0, uint32_t b1,
    float c0, float c1, float c2, float c3)
{
    asm volatile(
        "mma.sync.aligned.m16n8k16.row.col.f32.f16.f16.f32 "
        "{%0,%1,%2,%3},{%4,%5,%6,%7},{%8,%9},{%10,%11,%12,%13};"
        : "=f"(d0),"=f"(d1),"=f"(d2),"=f"(d3)
        : "r"(a0),"r"(a1),"r"(a2),"r"(a3),"r"(b0),"r"(b1),
          "f"(c0),"f"(c1),"f"(c2),"f"(c3));
}

__global__ __launch_bounds__(768, 1)
void attn_aug2d_mma(const float* __restrict__ inp,
                    const float* __restrict__ relw,
                    const float* __restrict__ relh,
                    float* __restrict__ out)
{
    extern __shared__ float sm[];
    float2* KT2 = (float2*)sm;
    uint2*  V2  = (uint2*)(sm + W_V2);
    const int tid  = threadIdx.x;
    const int warp = tid >> 5;
    const int lane = tid & 31;
    const int g    = lane >> 2;
    const int t    = lane & 3;
    const int strip = warp >> 3;        // 0..2
    const int mrow  = (warp & 7) << 4;
    const int h = blockIdx.y, b = blockIdx.z;
    const int qbase = blockIdx.x * QTQ;

    // ---- stage K transposed, interleaved (d, d+4) float2 per key ----
    for (int key = tid; key < Nn; key += 768){
        const float* p = inp + ((size_t)(b*Nn + key))*Cc + h*8 + 64;
        float4 k0 = *(const float4*)(p);
        float4 k1 = *(const float4*)(p + 4);
        KT2[0*KROW2 + key] = make_float2(tf32r(k0.x), tf32r(k1.x));
        KT2[1*KROW2 + key] = make_float2(tf32r(k0.y), tf32r(k1.y));
        KT2[2*KROW2 + key] = make_float2(tf32r(k0.z), tf32r(k1.z));
        KT2[3*KROW2 + key] = make_float2(tf32r(k0.w), tf32r(k1.w));
    }
    // ---- stage V as paired f16x2: entry e=(blk,t4) packs pairs (blk*8+t4, +4) ----
    for (int e = tid; e < 576; e += 768){
        int blk = e >> 2, t4 = e & 3;
        int p0 = blk*8 + t4, p1 = p0 + 4;
        const float* A0 = inp + ((size_t)(b*Nn + 2*p0))*Cc + h*8 + 128;
        const float* A1 = A0 + Cc;
        const float* B0 = inp + ((size_t)(b*Nn + 2*p1))*Cc + h*8 + 128;
        const float* B1 = B0 + Cc;
        float4 a0 = *(const float4*)A0, a0h = *(const float4*)(A0+4);
        float4 a1 = *(const float4*)A1, a1h = *(const float4*)(A1+4);
        float4 b0 = *(const float4*)B0, b0h = *(const float4*)(B0+4);
        float4 b1 = *(const float4*)B1, b1h = *(const float4*)(B1+4);
        V2[0*VROW2 + e] = make_uint2(pkh2(a0.x,a1.x),  pkh2(b0.x,b1.x));
        V2[1*VROW2 + e] = make_uint2(pkh2(a0.y,a1.y),  pkh2(b0.y,b1.y));
        V2[2*VROW2 + e] = make_uint2(pkh2(a0.z,a1.z),  pkh2(b0.z,b1.z));
        V2[3*VROW2 + e] = make_uint2(pkh2(a0.w,a1.w),  pkh2(b0.w,b1.w));
        V2[4*VROW2 + e] = make_uint2(pkh2(a0h.x,a1h.x),pkh2(b0h.x,b1h.x));
        V2[5*VROW2 + e] = make_uint2(pkh2(a0h.y,a1h.y),pkh2(b0h.y,b1h.y));
        V2[6*VROW2 + e] = make_uint2(pkh2(a0h.z,a1h.z),pkh2(b0h.z,b1h.z));
        V2[7*VROW2 + e] = make_uint2(pkh2(a0h.w,a1h.w),pkh2(b0h.w,b1h.w));
    }

    // ---- bias tables: broadcast-friendly mapping ----
    {
        const int q  = tid & 127;
        const int ck = tid >> 7;          // 0..5 — warp-uniform
        const int n  = qbase + q;
        const int x  = n / 48, y = n - x*48;
        const float* qp = inp + ((size_t)(b*Nn + n))*Cc + h*8;
        float4 q0 = *(const float4*)(qp);
        float4 q1 = *(const float4*)(qp + 4);
        const int isw  = (ck >= 3);
        const int pos0 = (ck - isw*3) * 16;
        const int roff = isw ? -y : -x;
        const float* relT = isw ? relw : relh;
        float* dst = isw ? (sm + W_PW + q*50) : (sm + W_PH + q*49);
        #pragma unroll 4
        for (int ii = 0; ii < 16; ii++){
            int pos = pos0 + ii;
            const float* rel = relT + (pos + roff + 47)*8;
            float4 r0 = *(const float4*)(rel);
            float4 r1 = *(const float4*)(rel + 4);
            float s = q0.x*r0.x + q0.y*r0.y + q0.z*r0.z + q0.w*r0.w
                    + q1.x*r1.x + q1.y*r1.y + q1.z*r1.z + q1.w*r1.w;
            dst[pos] = s * SL2E;
        }
    }

    // ---- Q fragment (GEMM1 A), tf32, pre-scaled ----
    const int qa = mrow + g, qb = qa + 8;
    const float* qpa = inp + ((size_t)(b*Nn + qbase + qa))*Cc + h*8;
    const float* qpb = inp + ((size_t)(b*Nn + qbase + qb))*Cc + h*8;
    const uint32_t aq0 = __float_as_uint(tf32r(qpa[t]   * SL2E));
    const uint32_t aq1 = __float_as_uint(tf32r(qpb[t]   * SL2E));
    const uint32_t aq2 = __float_as_uint(tf32r(qpa[t+4] * SL2E));
    const uint32_t aq3 = __float_as_uint(tf32r(qpb[t+4] * SL2E));

    __syncthreads();

    // ---- pw bias: tile-invariant -> hoist into registers ----
    float2 pal[3], pbl[3], pah[3], pbh[3];
    #pragma unroll
    for (int jj = 0; jj < 3; jj++){
        const int Y = 16*jj + 2*t;
        pal[jj] = *(const float2*)&sm[W_PW + qa*50 + Y];
        pbl[jj] = *(const float2*)&sm[W_PW + qb*50 + Y];
        pah[jj] = *(const float2*)&sm[W_PW + qa*50 + Y + 8];
        pbh[jj] = *(const float2*)&sm[W_PW + qb*50 + Y + 8];
    }

    float o0=0.f, o1=0.f, o2=0.f, o3=0.f;
    float s0=0.f, s1=0.f, s2=0.f, s3=0.f;   // softmax-sum fragment (ones-mma)

    for (int tile = 0; tile < NTILES; tile++){
        const int X     = 3*tile + strip;
        const int K0t   = tile*KTILE + strip*48;
        const int Vbase = tile*36 + strip*12;
        const float pha = sm[W_PH + qa*49 + X];
        const float phb = sm[W_PH + qb*49 + X];

        #pragma unroll
        for (int jj = 0; jj < 3; jj++){
            const int K0 = K0t + 16*jj;
            float2 kl = KT2[t*KROW2 + K0 + g];
            float2 kh = KT2[t*KROW2 + K0 + 8 + g];

            float l0,l1,l2,l3, h0,h1,h2,h3;
            mma_tf32c(l0,l1,l2,l3, aq0,aq1,aq2,aq3,
                      __float_as_uint(kl.x), __float_as_uint(kl.y),
                      pha + pal[jj].x, pha + pal[jj].y,
                      phb + pbl[jj].x, phb + pbl[jj].y);
            mma_tf32c(h0,h1,h2,h3, aq0,aq1,aq2,aq3,
                      __float_as_uint(kh.x), __float_as_uint(kh.y),
                      pha + pah[jj].x, pha + pah[jj].y,
                      phb + pbh[jj].x, phb + pbh[jj].y);

            // pack logits to f16x2, exponentiate in f16x2 (result IS the A-frag)
            uint32_t a0 = ex2h2(pkh2(l0, l1));
            uint32_t a1 = ex2h2(pkh2(l2, l3));
            uint32_t a2 = ex2h2(pkh2(h0, h1));
            uint32_t a3 = ex2h2(pkh2(h2, h3));

            uint2 vv = V2[g*VROW2 + Vbase + 4*jj + t];
            mma_f16(o0,o1,o2,o3, a0,a1,a2,a3, vv.x, vv.y, o0,o1,o2,o3);
            // softmax sums: B = all-ones -> D cols all equal the row sum
            mma_f16(s0,s1,s2,s3, a0,a1,a2,a3, ONES16, ONES16, s0,s1,s2,s3);
        }
    }

    // ---- sums already reduced across t-group by the ones-mma ----
    if (t == 0){
        sm[W_SS + strip*128 + qa] = s0;
        sm[W_SS + strip*128 + qb] = s2;
    }
    *(float2*)&sm[W_OS + strip*1024 + qa*8 + 2*t] = make_float2(o0, o1);
    *(float2*)&sm[W_OS + strip*1024 + qb*8 + 2*t] = make_float2(o2, o3);
    __syncthreads();

    // ---- combine strips, normalize, write ----
    if (tid < 128){
        int q = tid;
        float r = 1.0f / (sm[W_SS + q] + sm[W_SS + 128 + q] + sm[W_SS + 256 + q]);
        float* op = out + ((size_t)(b*Nn + qbase + q))*64 + h*8;
        #pragma unroll
        for (int half = 0; half < 2; half++){
            float4 A = *(float4*)&sm[W_OS +        q*8 + half*4];
            float4 B = *(float4*)&sm[W_OS + 1024 + q*8 + half*4];
            float4 C = *(float4*)&sm[W_OS + 2048 + q*8 + half*4];
            ((float4*)op)[half] = make_float4((A.x+B.x+C.x)*r, (A.y+B.y+C.y)*r,
                                              (A.z+B.z+C.z)*r, (A.w+B.w+C.w)*r);
        }
    }
}

extern "C" void kernel_launch(void* const* d_in, const int* in_sizes, int n_in,
                              void* d_out, int out_size)
{
    const float* inp  = (const float*)d_in[0];
    const float* relw = (const float*)d_in[1];
    const float* relh = (const float*)d_in[2];
    float* out = (float*)d_out;

    cudaFuncSetAttribute(attn_aug2d_mma,
                         cudaFuncAttributeMaxDynamicSharedMemorySize, SMEM_BYTES);
    dim3 grid(Nn/QTQ, 8, 2);
    attn_aug2d_mma<<<grid, 768, SMEM_BYTES>>>(inp, relw, relh, out);
}

// round 16
// speedup vs baseline: 1.9233x; 1.0525x over previous
#include <cuda_runtime.h>
#include <cuda_fp16.h>
#include <cstdint>

#define Nn 2304
#define Cc 192
#define QTQ 128        // queries per CTA
#define KTILE 144      // keys per tile (3 X-rows)
#define NTILES 16
#define KPROW 1160     // KP row stride in uint2 (==8 mod 16: conflict-free LDS.64)
#define VROW2 580      // V2 row stride in uint2  (==4 mod 16: conflict-free)
#define SL2E 0.5100420914154871f
#define ONES16 0x3C003C00u

// smem u32-word offsets
#define W_KP   0                       // uint2 [4][KPROW]: dims(2t,2t+1) x keys(k,k+8)
#define W_V2   (4*KPROW*2)             // uint2 [8][VROW2]
#define W_PH   (W_V2 + 8*VROW2*2)      // phT[128][49] f32
#define W_PW   (W_PH + 128*49)         // pwT[128][50] f32
#define W_OS   (W_PW + 128*50)         // O partials [3][128][8] f32
#define W_SS   (W_OS + 3*128*8)        // sums [3][128] f32
#define SMEM_BYTES ((W_SS + 3*128)*4)

__device__ __forceinline__ uint32_t pkh2(float lo, float hi){
    __half2 h = __floats2half2_rn(lo, hi);
    return *(uint32_t*)&h;
}
__device__ __forceinline__ uint32_t ex2h2(uint32_t x){
    uint32_t r; asm("ex2.approx.f16x2 %0,%1;" : "=r"(r) : "r"(x));
    return r;
}
// f16 m16n8k8 with f32 C/D (bias preloaded in C)
__device__ __forceinline__ void mma_f16k8(
    float& d0, float& d1, float& d2, float& d3,
    uint32_t a0, uint32_t a1, uint32_t b0,
    float c0, float c1, float c2, float c3)
{
    asm volatile(
        "mma.sync.aligned.m16n8k8.row.col.f32.f16.f16.f32 "
        "{%0,%1,%2,%3},{%4,%5},{%6},{%7,%8,%9,%10};"
        : "=f"(d0),"=f"(d1),"=f"(d2),"=f"(d3)
        : "r"(a0),"r"(a1),"r"(b0),
          "f"(c0),"f"(c1),"f"(c2),"f"(c3));
}
__device__ __forceinline__ void mma_f16(
    float& d0, float& d1, float& d2, float& d3,
    uint32_t a0, uint32_t a1, uint32_t a2, uint32_t a3,
    uint32_t b0, uint32_t b1,
    float c0, float c1, float c2, float c3)
{
    asm volatile(
        "mma.sync.aligned.m16n8k16.row.col.f32.f16.f16.f32 "
        "{%0,%1,%2,%3},{%4,%5,%6,%7},{%8,%9},{%10,%11,%12,%13};"
        : "=f"(d0),"=f"(d1),"=f"(d2),"=f"(d3)
        : "r"(a0),"r"(a1),"r"(a2),"r"(a3),"r"(b0),"r"(b1),
          "f"(c0),"f"(c1),"f"(c2),"f"(c3));
}

__global__ __launch_bounds__(768, 1)
void attn_aug2d_mma(const float* __restrict__ inp,
                    const float* __restrict__ relw,
                    const float* __restrict__ relh,
                    float* __restrict__ out)
{
    extern __shared__ float sm[];
    uint32_t* smu = (uint32_t*)sm;
    const uint2* KP2 = (const uint2*)(smu + W_KP);
    uint2*      V2  = (uint2*)(smu + W_V2);
    const int tid  = threadIdx.x;
    const int warp = tid >> 5;
    const int lane = tid & 31;
    const int g    = lane >> 2;
    const int t    = lane & 3;
    const int strip = warp >> 3;        // 0..2
    const int mrow  = (warp & 7) << 4;
    const int h = blockIdx.y, b = blockIdx.z;
    const int qbase = blockIdx.x * QTQ;

    // ---- stage K as paired f16x2: KP[dp][grp*8+lo] = (dims(2dp,2dp+1) of key, of key+8) ----
    for (int key = tid; key < Nn; key += 768){
        const float* p = inp + ((size_t)(b*Nn + key))*Cc + h*8 + 64;
        float4 k0 = *(const float4*)(p);
        float4 k1 = *(const float4*)(p + 4);
        int grp = key >> 4, r = key & 15;
        int base = W_KP + ((grp*8 + (r & 7)) << 1) + (r >> 3);
        smu[base + 0*KPROW*2] = pkh2(k0.x, k0.y);
        smu[base + 1*KPROW*2] = pkh2(k0.z, k0.w);
        smu[base + 2*KPROW*2] = pkh2(k1.x, k1.y);
        smu[base + 3*KPROW*2] = pkh2(k1.z, k1.w);
    }
    // ---- stage V as paired f16x2: entry e=(blk,t4) packs pairs (blk*8+t4, +4) ----
    for (int e = tid; e < 576; e += 768){
        int blk = e >> 2, t4 = e & 3;
        int p0 = blk*8 + t4, p1 = p0 + 4;
        const float* A0 = inp + ((size_t)(b*Nn + 2*p0))*Cc + h*8 + 128;
        const float* A1 = A0 + Cc;
        const float* B0 = inp + ((size_t)(b*Nn + 2*p1))*Cc + h*8 + 128;
        const float* B1 = B0 + Cc;
        float4 a0 = *(const float4*)A0, a0h = *(const float4*)(A0+4);
        float4 a1 = *(const float4*)A1, a1h = *(const float4*)(A1+4);
        float4 b0 = *(const float4*)B0, b0h = *(const float4*)(B0+4);
        float4 b1 = *(const float4*)B1, b1h = *(const float4*)(B1+4);
        V2[0*VROW2 + e] = make_uint2(pkh2(a0.x,a1.x),  pkh2(b0.x,b1.x));
        V2[1*VROW2 + e] = make_uint2(pkh2(a0.y,a1.y),  pkh2(b0.y,b1.y));
        V2[2*VROW2 + e] = make_uint2(pkh2(a0.z,a1.z),  pkh2(b0.z,b1.z));
        V2[3*VROW2 + e] = make_uint2(pkh2(a0.w,a1.w),  pkh2(b0.w,b1.w));
        V2[4*VROW2 + e] = make_uint2(pkh2(a0h.x,a1h.x),pkh2(b0h.x,b1h.x));
        V2[5*VROW2 + e] = make_uint2(pkh2(a0h.y,a1h.y),pkh2(b0h.y,b1h.y));
        V2[6*VROW2 + e] = make_uint2(pkh2(a0h.z,a1h.z),pkh2(b0h.z,b1h.z));
        V2[7*VROW2 + e] = make_uint2(pkh2(a0h.w,a1h.w),pkh2(b0h.w,b1h.w));
    }

    // ---- bias tables: broadcast-friendly mapping ----
    {
        const int q  = tid & 127;
        const int ck = tid >> 7;          // 0..5 — warp-uniform
        const int n  = qbase + q;
        const int x  = n / 48, y = n - x*48;
        const float* qp = inp + ((size_t)(b*Nn + n))*Cc + h*8;
        float4 q0 = *(const float4*)(qp);
        float4 q1 = *(const float4*)(qp + 4);
        const int isw  = (ck >= 3);
        const int pos0 = (ck - isw*3) * 16;
        const int roff = isw ? -y : -x;
        const float* relT = isw ? relw : relh;
        float* dst = isw ? (sm + W_PW + q*50) : (sm + W_PH + q*49);
        #pragma unroll 4
        for (int ii = 0; ii < 16; ii++){
            int pos = pos0 + ii;
            const float* rel = relT + (pos + roff + 47)*8;
            float4 r0 = *(const float4*)(rel);
            float4 r1 = *(const float4*)(rel + 4);
            float s = q0.x*r0.x + q0.y*r0.y + q0.z*r0.z + q0.w*r0.w
                    + q1.x*r1.x + q1.y*r1.y + q1.z*r1.z + q1.w*r1.w;
            dst[pos] = s * SL2E;
        }
    }

    // ---- Q fragment (GEMM1 A, f16): dims (2t, 2t+1) for rows qa, qb ----
    const int qa = mrow + g, qb = qa + 8;
    const float* qpa = inp + ((size_t)(b*Nn + qbase + qa))*Cc + h*8;
    const float* qpb = inp + ((size_t)(b*Nn + qbase + qb))*Cc + h*8;
    float2 qva = *(const float2*)(qpa + 2*t);
    float2 qvb = *(const float2*)(qpb + 2*t);
    const uint32_t aq0 = pkh2(qva.x * SL2E, qva.y * SL2E);
    const uint32_t aq1 = pkh2(qvb.x * SL2E, qvb.y * SL2E);

    __syncthreads();

    // ---- pw bias: tile-invariant -> hoist into registers ----
    float2 pal[3], pbl[3], pah[3], pbh[3];
    #pragma unroll
    for (int jj = 0; jj < 3; jj++){
        const int Y = 16*jj + 2*t;
        pal[jj] = *(const float2*)&sm[W_PW + qa*50 + Y];
        pbl[jj] = *(const float2*)&sm[W_PW + qb*50 + Y];
        pah[jj] = *(const float2*)&sm[W_PW + qa*50 + Y + 8];
        pbh[jj] = *(const float2*)&sm[W_PW + qb*50 + Y + 8];
    }

    float o0=0.f, o1=0.f, o2=0.f, o3=0.f;
    float s0=0.f, s1=0.f, s2=0.f, s3=0.f;   // softmax-sum fragment (ones-mma)

    for (int tile = 0; tile < NTILES; tile++){
        const int X     = 3*tile + strip;
        const int Gbase = tile*72 + strip*24;   // (K0/16)*8 base: 9 grps/tile * 8
        const int Vbase = tile*36 + strip*12;
        const float pha = sm[W_PH + qa*49 + X];
        const float phb = sm[W_PH + qb*49 + X];

        #pragma unroll
        for (int jj = 0; jj < 3; jj++){
            // both K octets in ONE LDS.64
            uint2 kp = KP2[t*KPROW + Gbase + 8*jj + g];

            float l0,l1,l2,l3, h0,h1,h2,h3;
            mma_f16k8(l0,l1,l2,l3, aq0,aq1, kp.x,
                      pha + pal[jj].x, pha + pal[jj].y,
                      phb + pbl[jj].x, phb + pbl[jj].y);
            mma_f16k8(h0,h1,h2,h3, aq0,aq1, kp.y,
                      pha + pah[jj].x, pha + pah[jj].y,
                      phb + pbh[jj].x, phb + pbh[jj].y);

            // pack logits to f16x2, exponentiate in f16x2 (result IS the A-frag)
            uint32_t a0 = ex2h2(pkh2(l0, l1));
            uint32_t a1 = ex2h2(pkh2(l2, l3));
            uint32_t a2 = ex2h2(pkh2(h0, h1));
            uint32_t a3 = ex2h2(pkh2(h2, h3));

            uint2 vv = V2[g*VROW2 + Vbase + 4*jj + t];
            mma_f16(o0,o1,o2,o3, a0,a1,a2,a3, vv.x, vv.y, o0,o1,o2,o3);
            mma_f16(s0,s1,s2,s3, a0,a1,a2,a3, ONES16, ONES16, s0,s1,s2,s3);
        }
    }

    // ---- sums already reduced across t-group by the ones-mma ----
    if (t == 0){
        sm[W_SS + strip*128 + qa] = s0;
        sm[W_SS + strip*128 + qb] = s2;
    }
    *(float2*)&sm[W_OS + strip*1024 + qa*8 + 2*t] = make_float2(o0, o1);
    *(float2*)&sm[W_OS + strip*1024 + qb*8 + 2*t] = make_float2(o2, o3);
    __syncthreads();

    // ---- combine strips, normalize, write ----
    if (tid < 128){
        int q = tid;
        float r = 1.0f / (sm[W_SS + q] + sm[W_SS + 128 + q] + sm[W_SS + 256 + q]);
        float* op = out + ((size_t)(b*Nn + qbase + q))*64 + h*8;
        #pragma unroll
        for (int half = 0; half < 2; half++){
            float4 A = *(float4*)&sm[W_OS +        q*8 + half*4];
            float4 B = *(float4*)&sm[W_OS + 1024 + q*8 + half*4];
            float4 C = *(float4*)&sm[W_OS + 2048 + q*8 + half*4];
            ((float4*)op)[half] = make_float4((A.x+B.x+C.x)*r, (A.y+B.y+C.y)*r,
                                              (A.z+B.z+C.z)*r, (A.w+B.w+C.w)*r);
        }
    }
}

extern "C" void kernel_launch(void* const* d_in, const int* in_sizes, int n_in,
                              void* d_out, int out_size)
{
    const float* inp  = (const float*)d_in[0];
    const float* relw = (const float*)d_in[1];
    const float* relh = (const float*)d_in[2];
    float* out = (float*)d_out;

    cudaFuncSetAttribute(attn_aug2d_mma,
                         cudaFuncAttributeMaxDynamicSharedMemorySize, SMEM_BYTES);
    dim3 grid(Nn/QTQ, 8, 2);
    attn_aug2d_mma<<<grid, 768, SMEM_BYTES>>>(inp, relw, relh, out);
}